// round 5
// baseline (speedup 1.0000x reference)
#include <cuda_runtime.h>
#include <cstdint>

#define B_ 32
#define T_ 1024
#define V_ 1000
#define L_ 128
#define NG_ 256           // time groups of 4 steps
#define SLOTS_ 129        // slot k = pair k (0..127), 128 = blank
#define NEGF (-1e30f)
#define L2E_ 1.4426950408889634f
#define LN2_ 0.6931471805599453f

// scratch (allocation-free rule: __device__ globals)
// emissions, DP-native layout: [b][g][slot][4 timesteps], log2 domain
__device__ float g_E2[(size_t)B_ * NG_ * SLOTS_ * 4];
__device__ float g_partial[B_];

__device__ __forceinline__ float ex2f_(float x){ float y; asm("ex2.approx.f32 %0,%1;":"=f"(y):"f"(x)); return y; }
__device__ __forceinline__ float lg2f_(float x){ float y; asm("lg2.approx.f32 %0,%1;":"=f"(y):"f"(x)); return y; }

// ---------------------------------------------------------------------------
// K1: warp per (b,t) row: log2-softmax + gather of 129 tokens, staged through
// smem, written out as coalesced [b][g][slot][4] chunks (2 groups/block).
// Invalid-label rows (k >= tlen[b]) poisoned to NEGF -> K2 needs no masking.
// ---------------------------------------------------------------------------
__global__ void __launch_bounds__(256) k1_emit(const float* __restrict__ pred,
                                               const int* __restrict__ target,
                                               const int* __restrict__ tlen){
    __shared__ float sE[SLOTS_ * 12];          // [slot][tloc(8) pad->12]
    const int wid  = threadIdx.x >> 5;
    const int lane = threadIdx.x & 31;
    const int w    = blockIdx.x * 8 + wid;     // flat row = b*T + t
    const int b    = w >> 10;
    const int t    = w & (T_ - 1);
    const int tloc = t & 7;
    const int g0   = (t & ~7) >> 2;            // first of this block's 2 groups
    const float* p = pred + (size_t)w * V_;
    const int tl   = tlen[b];

    float4 v[8];
    float m = NEGF;
    #pragma unroll
    for (int k = 0; k < 8; k++){
        const int i4 = lane + 32 * k;
        if (i4 < 250){
            v[k] = reinterpret_cast<const float4*>(p)[i4];
            m = fmaxf(m, fmaxf(fmaxf(v[k].x, v[k].y), fmaxf(v[k].z, v[k].w)));
        } else {
            v[k] = make_float4(NEGF, NEGF, NEGF, NEGF);
        }
    }
    #pragma unroll
    for (int o = 16; o; o >>= 1) m = fmaxf(m, __shfl_xor_sync(~0u, m, o));

    float s = 0.f;
    #pragma unroll
    for (int k = 0; k < 8; k++){
        s += ex2f_((v[k].x - m) * L2E_) + ex2f_((v[k].y - m) * L2E_)
           + ex2f_((v[k].z - m) * L2E_) + ex2f_((v[k].w - m) * L2E_);
    }
    #pragma unroll
    for (int o = 16; o; o >>= 1) s += __shfl_xor_sync(~0u, s, o);
    const float lg2s = lg2f_(s);

    const int* tg = target + b * L_;
    #pragma unroll
    for (int r = lane; r < SLOTS_; r += 32){
        int slot; float val;
        if (r == 0){
            slot = 128;                                     // blank (token 0)
            val  = (p[0] - m) * L2E_ - lg2s;
        } else {
            const int k = r - 1;                            // pair index
            slot = k;
            val  = (k < tl) ? ((p[tg[k]] - m) * L2E_ - lg2s) : NEGF;
        }
        sE[slot * 12 + tloc] = val;
    }
    __syncthreads();
    for (int k = threadIdx.x; k < 2 * SLOTS_; k += 256){
        const int gg = (k >= SLOTS_) ? 1 : 0;
        const int sl = k - gg * SLOTS_;
        const float4 o = *reinterpret_cast<const float4*>(&sE[sl * 12 + gg * 4]);
        reinterpret_cast<float4*>(g_E2)[((size_t)b * NG_ + g0 + gg) * SLOTS_ + sl] = o;
    }
}

// ---------------------------------------------------------------------------
// K2: W-CTC forward DP, 4 warps per batch in a time-skewed wavefront.
// Thread tid owns pair k = tid (blank s=2k+1, label s=2k+2); warp w processes
// time-group g at iteration g+w. The only cross-warp dependency is warp w-1's
// lane-31 label at t-1, passed through a 16-deep smem ring; by the skew it is
// always >= 1 iteration (one __syncthreads) old when consumed.
// Star state alpha[0] == 0 forever; end-star deferred to a final reduction
// over per-step (alpha_t[ll], alpha_t[lb]) stored in smem.
// ---------------------------------------------------------------------------
__global__ void __launch_bounds__(128) k2_dp(const int* __restrict__ target,
                                             const int* __restrict__ tlen){
    __shared__ float sll[T_], slb[T_];
    __shared__ float sBnd[4][16];              // [warp][t & 15] boundary labels
    __shared__ float red[4];
    const int b    = blockIdx.x;
    const int tid  = threadIdx.x;
    const int wid  = tid >> 5;
    const int lane = tid & 31;
    const int tl   = tlen[b];                  // in [64,128]
    const int* tg  = target + b * L_;
    const int k    = tid;                      // pair index

    const float sk = (k == 0 || tg[k] != tg[k - 1]) ? 1.0f : 0.0f;

    // owners of ll / lb states (tid == pair index makes this trivial)
    const bool wll   = (tid == tl - 1);        // label of pair tl-1
    const bool lbp   = (tl < 128);
    const bool wlb   = lbp ? (tid == tl) : (tid == 127);
    const bool w3l31 = (tid == 127);           // owns final blank bF (s=257)

    if (tid < 64) (&sBnd[0][0])[tid] = NEGF;
    __syncthreads();

    const float4* __restrict__ ch =
        reinterpret_cast<const float4*>(g_E2) + (size_t)b * NG_ * SLOTS_;

    float bq = NEGF, lq = NEGF, bF = NEGF;
    float4 pb, pl;                             // prefetched next group

    for (int i = 0; i < NG_ + 3; i++){
        const int g = i - wid;
        if (0 <= g && g < NG_){
            float4 cb, cl;
            if (g == 0){ cb = ch[128]; cl = ch[32 * wid + lane]; }
            else       { cb = pb;      cl = pl; }
            if (g + 1 < NG_){
                const float4* cn = ch + (size_t)(g + 1) * SLOTS_;
                pb = cn[128]; pl = cn[32 * wid + lane];
            }
            // boundary values for this group (all already in the ring)
            float rq0 = NEGF, rq1 = NEGF, rq2 = NEGF, rq3 = NEGF;
            if (lane == 0 && wid > 0){
                const int tb = 4 * g - 1;
                rq0 = (tb >= 0) ? sBnd[wid - 1][tb & 15] : NEGF;
                rq1 = sBnd[wid - 1][(tb + 1) & 15];
                rq2 = sBnd[wid - 1][(tb + 2) & 15];
                rq3 = sBnd[wid - 1][(tb + 3) & 15];
            }

            auto step = [&](float eb, float el, float rlp, int t){
                float lp = __shfl_up_sync(0xffffffffu, lq, 1);
                if (lane == 0) lp = (wid == 0) ? 0.0f : rlp;   // star = 0
                if (w3l31){                                    // bF from OLD lq
                    const float mm = fmaxf(bF, lq);
                    bF = eb + mm + lg2f_(ex2f_(bF - mm) + ex2f_(lq - mm));
                }
                const float m  = fmaxf(fmaxf(lq, bq), lp);
                const float u  = ex2f_(bq - m);
                const float vv = ex2f_(lp - m);
                const float w  = ex2f_(lq - m);
                bq = eb + m + lg2f_(u + vv);
                lq = el + m + lg2f_(fmaf(vv, sk, w + u));
                if (lane == 31) sBnd[wid][t & 15] = lq;
                if (wll) sll[t] = lq;
                if (wlb) slb[t] = lbp ? bq : bF;
            };

            if (g == 0){
                if (tid == 0){ bq = cb.x; lq = cl.x; }         // alpha0[1],[2]
                if (lane == 31) sBnd[wid][0] = lq;             // == NEGF
                if (wll) sll[0] = NEGF;                        // ll,lb invalid at t=0
                if (wlb) slb[0] = NEGF;
                step(cb.y, cl.y, rq1, 1);
                step(cb.z, cl.z, rq2, 2);
                step(cb.w, cl.w, rq3, 3);
            } else {
                const int t0 = 4 * g;
                step(cb.x, cl.x, rq0, t0);
                step(cb.y, cl.y, rq1, t0 + 1);
                step(cb.z, cl.z, rq2, t0 + 2);
                step(cb.w, cl.w, rq3, t0 + 3);
            }
        }
        __syncthreads();
    }

    // final reduction: total = lse over 2048 stored values (128 threads)
    float m = NEGF;
    for (int t = tid; t < T_; t += 128) m = fmaxf(m, fmaxf(sll[t], slb[t]));
    #pragma unroll
    for (int o = 16; o; o >>= 1) m = fmaxf(m, __shfl_xor_sync(~0u, m, o));
    if (lane == 0) red[wid] = m;
    __syncthreads();
    m = fmaxf(fmaxf(red[0], red[1]), fmaxf(red[2], red[3]));
    float s = 0.f;
    for (int t = tid; t < T_; t += 128) s += ex2f_(sll[t] - m) + ex2f_(slb[t] - m);
    #pragma unroll
    for (int o = 16; o; o >>= 1) s += __shfl_xor_sync(~0u, s, o);
    __syncthreads();
    if (lane == 0) red[wid] = s;
    __syncthreads();
    if (tid == 0){
        const float tot2 = m + lg2f_(red[0] + red[1] + red[2] + red[3]);
        g_partial[b] = (-tot2 * LN2_) / (float)tl;
    }
}

// ---------------------------------------------------------------------------
// K3: mean over batches -> scalar
// ---------------------------------------------------------------------------
__global__ void k3_final(float* __restrict__ out){
    float v = (threadIdx.x < B_) ? g_partial[threadIdx.x] : 0.f;
    #pragma unroll
    for (int o = 16; o; o >>= 1) v += __shfl_xor_sync(~0u, v, o);
    if (threadIdx.x == 0) out[0] = v / (float)B_;
}

extern "C" void kernel_launch(void* const* d_in, const int* in_sizes, int n_in,
                              void* d_out, int out_size) {
    const float* pred   = (const float*)d_in[0];   // (B,T,V) f32
    const int*   target = (const int*)d_in[1];     // (B,L) i32
    const int*   tlen   = (const int*)d_in[2];     // (B,) i32
    (void)in_sizes; (void)n_in; (void)out_size;

    k1_emit<<<B_ * T_ / 8, 256>>>(pred, target, tlen);
    k2_dp<<<B_, 128>>>(target, tlen);
    k3_final<<<1, 32>>>((float*)d_out);
}

// round 6
// speedup vs baseline: 1.0291x; 1.0291x over previous
#include <cuda_runtime.h>
#include <cstdint>

#define B_ 32
#define T_ 1024
#define V_ 1000
#define L_ 128
#define NG_ 256           // time groups of 4 steps
#define SLOTS_ 129        // slot k = pair k (0..127), 128 = blank
#define NEGF (-1e30f)
#define L2E_ 1.4426950408889634f
#define LN2_ 0.6931471805599453f

// scratch (allocation-free rule: __device__ globals)
// emissions, DP-native layout: [b][g][slot][4 timesteps], log2 domain
__device__ float g_E2[(size_t)B_ * NG_ * SLOTS_ * 4];
__device__ float g_partial[B_];

__device__ __forceinline__ float ex2f_(float x){ float y; asm("ex2.approx.f32 %0,%1;":"=f"(y):"f"(x)); return y; }
__device__ __forceinline__ float lg2f_(float x){ float y; asm("lg2.approx.f32 %0,%1;":"=f"(y):"f"(x)); return y; }

__device__ __forceinline__ int ld_acq_(const int* p){
    int v; asm volatile("ld.acquire.cta.b32 %0, [%1];" : "=r"(v) : "l"(p) : "memory"); return v;
}
__device__ __forceinline__ void st_rel_(int* p, int v){
    asm volatile("st.release.cta.b32 [%0], %1;" :: "l"(p), "r"(v) : "memory");
}

// ---------------------------------------------------------------------------
// K1: warp per (b,t) row: log2-softmax + gather of 129 tokens, staged through
// smem, written out as coalesced [b][g][slot][4] chunks (2 groups/block).
// Invalid-label rows (k >= tlen[b]) poisoned to NEGF -> K2 needs no masking.
// ---------------------------------------------------------------------------
__global__ void __launch_bounds__(256) k1_emit(const float* __restrict__ pred,
                                               const int* __restrict__ target,
                                               const int* __restrict__ tlen){
    __shared__ float sE[SLOTS_ * 12];          // [slot][tloc(8) pad->12]
    const int wid  = threadIdx.x >> 5;
    const int lane = threadIdx.x & 31;
    const int w    = blockIdx.x * 8 + wid;     // flat row = b*T + t
    const int b    = w >> 10;
    const int t    = w & (T_ - 1);
    const int tloc = t & 7;
    const int g0   = (t & ~7) >> 2;            // first of this block's 2 groups
    const float* p = pred + (size_t)w * V_;
    const int tl   = tlen[b];

    float4 v[8];
    float m = NEGF;
    #pragma unroll
    for (int k = 0; k < 8; k++){
        const int i4 = lane + 32 * k;
        if (i4 < 250){
            v[k] = reinterpret_cast<const float4*>(p)[i4];
            m = fmaxf(m, fmaxf(fmaxf(v[k].x, v[k].y), fmaxf(v[k].z, v[k].w)));
        } else {
            v[k] = make_float4(NEGF, NEGF, NEGF, NEGF);
        }
    }
    #pragma unroll
    for (int o = 16; o; o >>= 1) m = fmaxf(m, __shfl_xor_sync(~0u, m, o));

    float s = 0.f;
    #pragma unroll
    for (int k = 0; k < 8; k++){
        s += ex2f_((v[k].x - m) * L2E_) + ex2f_((v[k].y - m) * L2E_)
           + ex2f_((v[k].z - m) * L2E_) + ex2f_((v[k].w - m) * L2E_);
    }
    #pragma unroll
    for (int o = 16; o; o >>= 1) s += __shfl_xor_sync(~0u, s, o);
    const float lg2s = lg2f_(s);

    const int* tg = target + b * L_;
    #pragma unroll
    for (int r = lane; r < SLOTS_; r += 32){
        int slot; float val;
        if (r == 0){
            slot = 128;                                     // blank (token 0)
            val  = (p[0] - m) * L2E_ - lg2s;
        } else {
            const int k = r - 1;                            // pair index
            slot = k;
            val  = (k < tl) ? ((p[tg[k]] - m) * L2E_ - lg2s) : NEGF;
        }
        sE[slot * 12 + tloc] = val;
    }
    __syncthreads();
    for (int k = threadIdx.x; k < 2 * SLOTS_; k += 256){
        const int gg = (k >= SLOTS_) ? 1 : 0;
        const int sl = k - gg * SLOTS_;
        const float4 o = *reinterpret_cast<const float4*>(&sE[sl * 12 + gg * 4]);
        reinterpret_cast<float4*>(g_E2)[((size_t)b * NG_ + g0 + gg) * SLOTS_ + sl] = o;
    }
}

// ---------------------------------------------------------------------------
// K2: W-CTC forward DP, 4 warps per batch, SELF-TIMED wavefront (no barrier).
// Thread tid owns pair k = tid (blank s=2k+1, label s=2k+2). The only
// cross-warp dependency is warp w-1's lane-31 label at t-1. Boundary values
// go to a full-depth smem array sBnd[w][t]; lane 31 publishes a monotonic
// progress counter with st.release.cta after each 4-step group; consumer
// lane 0 spins with ld.acquire.cta once per group. Steady state: acquire
// passes immediately, each warp runs at its own chain speed, skewed 1 group.
// Star state alpha[0] == 0 forever; end-star deferred to a final lse over
// per-step (alpha_t[ll], alpha_t[lb]) stored in smem.
// ---------------------------------------------------------------------------
__global__ void __launch_bounds__(128) k2_dp(const int* __restrict__ target,
                                             const int* __restrict__ tlen){
    __shared__ float sll[T_], slb[T_];
    __shared__ float sBnd[3][T_];              // boundary labels of warps 0..2
    __shared__ int   sProg[3];                 // completed steps of warps 0..2
    __shared__ float red[4];
    const int b    = blockIdx.x;
    const int tid  = threadIdx.x;
    const int wid  = tid >> 5;
    const int lane = tid & 31;
    const int tl   = tlen[b];                  // in [64,128]
    const int* tg  = target + b * L_;

    const float sk = (tid == 0 || tg[tid] != tg[tid - 1]) ? 1.0f : 0.0f;

    const bool wll = (tid == tl - 1);          // label of pair tl-1
    const bool lbp = (tl < 128);
    const bool wlb = lbp ? (tid == tl) : (tid == 127);
    const bool wbF = (tid == 127);             // owns final blank bF (s=257)
    const bool prod = (wid < 3) && (lane == 31);

    if (tid < 3) sProg[tid] = 0;
    __syncthreads();

    const float4* __restrict__ ch =
        reinterpret_cast<const float4*>(g_E2) + (size_t)b * NG_ * SLOTS_;
    const int myslot = 32 * wid + lane;

    float bq = NEGF, lq = NEGF, bF = NEGF;
    float4 pb, pl;

    auto step = [&](float eb, float el, float rlp, int t){
        float lp = __shfl_up_sync(0xffffffffu, lq, 1);
        if (lane == 0) lp = (wid == 0) ? 0.0f : rlp;       // star = 0
        if (wbF){                                          // bF from OLD lq
            const float mm = fmaxf(bF, lq);
            bF = eb + mm + lg2f_(ex2f_(bF - mm) + ex2f_(lq - mm));
        }
        const float m  = fmaxf(fmaxf(lq, bq), lp);
        const float u  = ex2f_(bq - m);
        const float vv = ex2f_(lp - m);
        const float w  = ex2f_(lq - m);
        bq = eb + m + lg2f_(u + vv);
        lq = el + m + lg2f_(fmaf(vv, sk, w + u));
        if (prod) sBnd[wid][t] = lq;
        if (wll) sll[t] = lq;
        if (wlb) slb[t] = lbp ? bq : bF;
    };

    for (int g = 0; g < NG_; g++){
        float4 cb, cl;
        if (g == 0){ cb = ch[128]; cl = ch[myslot]; }
        else       { cb = pb;      cl = pl; }
        if (g + 1 < NG_){
            const float4* cn = ch + (size_t)(g + 1) * SLOTS_;
            pb = cn[128]; pl = cn[myslot];
        }

        float rq0 = NEGF, rq1 = NEGF, rq2 = NEGF, rq3 = NEGF;
        if (wid > 0){
            if (lane == 0){
                const int need = 4 * g + 3;                // boundary t=4g+2 done
                while (ld_acq_(&sProg[wid - 1]) < need) { }
                const int tb = 4 * g - 1;
                rq0 = (tb >= 0) ? sBnd[wid - 1][tb] : NEGF;
                rq1 = sBnd[wid - 1][tb + 1];
                rq2 = sBnd[wid - 1][tb + 2];
                rq3 = sBnd[wid - 1][tb + 3];
            }
            __syncwarp();
        }

        if (g == 0){
            if (tid == 0){ bq = cb.x; lq = cl.x; }         // alpha0[1], alpha0[2]
            if (prod) sBnd[wid][0] = lq;                   // == NEGF
            if (wll) sll[0] = NEGF;
            if (wlb) slb[0] = NEGF;
            step(cb.y, cl.y, rq1, 1);
            step(cb.z, cl.z, rq2, 2);
            step(cb.w, cl.w, rq3, 3);
        } else {
            const int t0 = 4 * g;
            step(cb.x, cl.x, rq0, t0);
            step(cb.y, cl.y, rq1, t0 + 1);
            step(cb.z, cl.z, rq2, t0 + 2);
            step(cb.w, cl.w, rq3, t0 + 3);
        }
        if (prod) st_rel_(&sProg[wid], 4 * g + 4);         // lane31 stored sBnd, publishes
    }

    __syncthreads();

    // final reduction: total = lse over 2048 stored values (128 threads)
    float m = NEGF;
    for (int t = tid; t < T_; t += 128) m = fmaxf(m, fmaxf(sll[t], slb[t]));
    #pragma unroll
    for (int o = 16; o; o >>= 1) m = fmaxf(m, __shfl_xor_sync(~0u, m, o));
    if (lane == 0) red[wid] = m;
    __syncthreads();
    m = fmaxf(fmaxf(red[0], red[1]), fmaxf(red[2], red[3]));
    float s = 0.f;
    for (int t = tid; t < T_; t += 128) s += ex2f_(sll[t] - m) + ex2f_(slb[t] - m);
    #pragma unroll
    for (int o = 16; o; o >>= 1) s += __shfl_xor_sync(~0u, s, o);
    __syncthreads();
    if (lane == 0) red[wid] = s;
    __syncthreads();
    if (tid == 0){
        const float tot2 = m + lg2f_(red[0] + red[1] + red[2] + red[3]);
        g_partial[b] = (-tot2 * LN2_) / (float)tl;
    }
}

// ---------------------------------------------------------------------------
// K3: mean over batches -> scalar
// ---------------------------------------------------------------------------
__global__ void k3_final(float* __restrict__ out){
    float v = (threadIdx.x < B_) ? g_partial[threadIdx.x] : 0.f;
    #pragma unroll
    for (int o = 16; o; o >>= 1) v += __shfl_xor_sync(~0u, v, o);
    if (threadIdx.x == 0) out[0] = v / (float)B_;
}

extern "C" void kernel_launch(void* const* d_in, const int* in_sizes, int n_in,
                              void* d_out, int out_size) {
    const float* pred   = (const float*)d_in[0];   // (B,T,V) f32
    const int*   target = (const int*)d_in[1];     // (B,L) i32
    const int*   tlen   = (const int*)d_in[2];     // (B,) i32
    (void)in_sizes; (void)n_in; (void)out_size;

    k1_emit<<<B_ * T_ / 8, 256>>>(pred, target, tlen);
    k2_dp<<<B_, 128>>>(target, tlen);
    k3_final<<<1, 32>>>((float*)d_out);
}

// round 7
// speedup vs baseline: 1.3274x; 1.2899x over previous
#include <cuda_runtime.h>
#include <cstdint>

#define B_ 32
#define T_ 1024
#define V_ 1000
#define L_ 128
#define NG_ 256           // time groups of 4 steps
#define SLOTS_ 129        // emission slots (see mapping below), 128 = blank
#define NEGF (-1e30f)
#define L2E_ 1.4426950408889634f
#define LN2_ 0.6931471805599453f

// scratch (allocation-free rule: __device__ globals)
// emissions, DP-native layout: [b][g][slot][4 timesteps], log2 domain
__device__ float g_E2[(size_t)B_ * NG_ * SLOTS_ * 4];
__device__ float g_partial[B_];

__device__ __forceinline__ float ex2f_(float x){ float y; asm("ex2.approx.f32 %0,%1;":"=f"(y):"f"(x)); return y; }
__device__ __forceinline__ float lg2f_(float x){ float y; asm("lg2.approx.f32 %0,%1;":"=f"(y):"f"(x)); return y; }
__device__ __forceinline__ float lse2_(float x, float y){
    float m = fmaxf(x, y);
    float d = fminf(x, y) - m;
    return m + lg2f_(1.0f + ex2f_(d));
}
__device__ __forceinline__ int ld_acq_(const int* p){
    int v; asm volatile("ld.acquire.cta.b32 %0, [%1];" : "=r"(v) : "l"(p) : "memory"); return v;
}
__device__ __forceinline__ void st_rel_(int* p, int v){
    asm volatile("st.release.cta.b32 [%0], %1;" :: "l"(p), "r"(v) : "memory");
}

// Emission slot for pair k (k = 0..127):
//   k <  64: slot = (k&1)*32 + (k>>1)          (warp A: lane = k>>1, j = k&1)
//   k >= 64: slot = 64 + (k&1)*32 + ((k-64)>>1) (warp B)
// slot 128 = blank.

// ---------------------------------------------------------------------------
// K1: warp per (b,t) row: log2-softmax + gather of 129 tokens, staged through
// smem, written out as coalesced [b][g][slot][4] chunks (2 groups/block).
// Invalid-label rows (k >= tlen[b]) poisoned to NEGF -> K2 needs no masking.
// ---------------------------------------------------------------------------
__global__ void __launch_bounds__(256) k1_emit(const float* __restrict__ pred,
                                               const int* __restrict__ target,
                                               const int* __restrict__ tlen){
    __shared__ float sE[SLOTS_ * 12];          // [slot][tloc(8) pad->12]
    const int wid  = threadIdx.x >> 5;
    const int lane = threadIdx.x & 31;
    const int w    = blockIdx.x * 8 + wid;     // flat row = b*T + t
    const int b    = w >> 10;
    const int t    = w & (T_ - 1);
    const int tloc = t & 7;
    const int g0   = (t & ~7) >> 2;            // first of this block's 2 groups
    const float* p = pred + (size_t)w * V_;
    const int tl   = tlen[b];

    float4 v[8];
    float m = NEGF;
    #pragma unroll
    for (int k = 0; k < 8; k++){
        const int i4 = lane + 32 * k;
        if (i4 < 250){
            v[k] = reinterpret_cast<const float4*>(p)[i4];
            m = fmaxf(m, fmaxf(fmaxf(v[k].x, v[k].y), fmaxf(v[k].z, v[k].w)));
        } else {
            v[k] = make_float4(NEGF, NEGF, NEGF, NEGF);
        }
    }
    #pragma unroll
    for (int o = 16; o; o >>= 1) m = fmaxf(m, __shfl_xor_sync(~0u, m, o));

    float s = 0.f;
    #pragma unroll
    for (int k = 0; k < 8; k++){
        s += ex2f_((v[k].x - m) * L2E_) + ex2f_((v[k].y - m) * L2E_)
           + ex2f_((v[k].z - m) * L2E_) + ex2f_((v[k].w - m) * L2E_);
    }
    #pragma unroll
    for (int o = 16; o; o >>= 1) s += __shfl_xor_sync(~0u, s, o);
    const float lg2s = lg2f_(s);

    const int* tg = target + b * L_;
    #pragma unroll
    for (int r = lane; r < SLOTS_; r += 32){
        int slot; float val;
        if (r == 0){
            slot = 128;                                     // blank (token 0)
            val  = (p[0] - m) * L2E_ - lg2s;
        } else {
            const int k = r - 1;                            // pair index
            slot = (k < 64) ? (((k & 1) << 5) + (k >> 1))
                            : (64 + ((k & 1) << 5) + ((k - 64) >> 1));
            val  = (k < tl) ? ((p[tg[k]] - m) * L2E_ - lg2s) : NEGF;
        }
        sE[slot * 12 + tloc] = val;
    }
    __syncthreads();
    for (int k = threadIdx.x; k < 2 * SLOTS_; k += 256){
        const int gg = (k >= SLOTS_) ? 1 : 0;
        const int sl = k - gg * SLOTS_;
        const float4 o = *reinterpret_cast<const float4*>(&sE[sl * 12 + gg * 4]);
        reinterpret_cast<float4*>(g_E2)[((size_t)b * NG_ + g0 + gg) * SLOTS_ + sl] = o;
    }
}

// ---------------------------------------------------------------------------
// K2: W-CTC forward DP, 2 warps per batch, 2 pairs per lane.
// Warp A: pairs 0-63, warp B: pairs 64-127, B lagging A by one 16-step chunk.
// A's lane 31 writes the pair-63 label boundary to sBnd[t] each step and
// publishes a progress counter (st.release) once per chunk; B's lane 0 waits
// (ld.acquire) once per chunk and reads boundaries with plain LDS.
// Star state alpha[0] == 0 forever. Final blank bF (s=257, only for tl=128)
// is removed from the loop and reconstructed post-loop from sll + blank
// emissions via prefix/suffix scans. End-star deferred to final lse over
// per-step (alpha_t[ll], alpha_t[lb]) in smem.
// ---------------------------------------------------------------------------
__global__ void __launch_bounds__(64) k2_dp(const int* __restrict__ target,
                                            const int* __restrict__ tlen){
    __shared__ float sll[T_], slb[T_], sBnd[T_];
    __shared__ float red[2], sX[2];
    __shared__ int   sProg;
    const int b    = blockIdx.x;
    const int tid  = threadIdx.x;
    const int wid  = tid >> 5;
    const int lane = tid & 31;
    const int tl   = tlen[b];                  // in [64,128]
    const int* tg  = target + b * L_;

    const int k0 = (wid == 0) ? 2 * lane : 64 + 2 * lane;   // my pair j=0
    const float sk0 = (k0 == 0 || tg[k0] != tg[k0 - 1]) ? 1.0f : 0.0f;
    const float sk1 = (tg[k0 + 1] != tg[k0]) ? 1.0f : 0.0f;

    const bool lbp  = (tl < 128);
    const bool wll0 = (k0 == tl - 1), wll1 = (k0 + 1 == tl - 1);
    const bool wlb0 = lbp && (k0 == tl), wlb1 = lbp && (k0 + 1 == tl);
    const bool bnd  = (wid == 0 && lane == 31);             // pair-63 owner

    if (tid == 0) sProg = 0;
    __syncthreads();

    const float4* __restrict__ ch =
        reinterpret_cast<const float4*>(g_E2) + (size_t)b * NG_ * SLOTS_;
    const int sl0 = 64 * wid + lane;           // slot of pair j=0
    const int sl1 = sl0 + 32;                  // slot of pair j=1

    float bq0 = NEGF, lq0 = NEGF, bq1 = NEGF, lq1 = NEGF;
    float4 cb, c0, c1, pb, p0, p1;

    auto step = [&](float eb, float e0, float e1, float rb, int t){
        float sh = __shfl_up_sync(0xffffffffu, lq1, 1);
        const float lp0 = (lane == 0) ? ((wid == 0) ? 0.0f : rb) : sh;
        const float lp1 = lq0;
        const float m0 = fmaxf(fmaxf(lq0, bq0), lp0);
        const float u0 = ex2f_(bq0 - m0), v0 = ex2f_(lp0 - m0), w0 = ex2f_(lq0 - m0);
        const float m1 = fmaxf(fmaxf(lq1, bq1), lp1);
        const float u1 = ex2f_(bq1 - m1), v1 = ex2f_(lp1 - m1), w1 = ex2f_(lq1 - m1);
        bq0 = eb + m0 + lg2f_(u0 + v0);
        lq0 = e0 + m0 + lg2f_(fmaf(v0, sk0, w0 + u0));
        bq1 = eb + m1 + lg2f_(u1 + v1);
        lq1 = e1 + m1 + lg2f_(fmaf(v1, sk1, w1 + u1));
        if (bnd) sBnd[t] = lq1;
        if (wll0 | wll1) sll[t] = wll1 ? lq1 : lq0;
        if (wlb0 | wlb1) slb[t] = wlb1 ? bq1 : bq0;
    };

    // ---- peeled group 0 ----
    if (wid == 1 && lane == 0){                // chunk-0 wait: need sBnd[0..14]
        while (ld_acq_(&sProg) < 16) { }
    }
    if (wid == 1) __syncwarp();
    cb = ch[128]; c0 = ch[sl0]; c1 = ch[sl1];
    pb = ch[SLOTS_ + 128]; p0 = ch[SLOTS_ + sl0]; p1 = ch[SLOTS_ + sl1];
    if (tid == 0){ bq0 = cb.x; lq0 = c0.x; sll[0] = NEGF; slb[0] = NEGF; }
    if (bnd) sBnd[0] = lq1;                    // NEGF
    {
        float rb1 = 0.f, rb2 = 0.f, rb3 = 0.f;
        if (wid == 1 && lane == 0){ rb1 = sBnd[0]; rb2 = sBnd[1]; rb3 = sBnd[2]; }
        step(cb.y, c0.y, c1.y, rb1, 1);
        step(cb.z, c0.z, c1.z, rb2, 2);
        step(cb.w, c0.w, c1.w, rb3, 3);
    }

    for (int g = 1; g < NG_; g++){
        if (wid == 1 && (g & 3) == 0){         // chunk wait, once per 16 steps
            if (lane == 0){
                int need = 4 * (g + 4); if (need > T_) need = T_;
                while (ld_acq_(&sProg) < need) { }
            }
            __syncwarp();
        }
        cb = pb; c0 = p0; c1 = p1;
        if (g + 1 < NG_){
            const float4* cn = ch + (size_t)(g + 1) * SLOTS_;
            pb = cn[128]; p0 = cn[sl0]; p1 = cn[sl1];
        }
        float rb0 = 0.f, rb1 = 0.f, rb2 = 0.f, rb3 = 0.f;
        if (wid == 1 && lane == 0){
            rb0 = sBnd[4 * g - 1]; rb1 = sBnd[4 * g];
            rb2 = sBnd[4 * g + 1]; rb3 = sBnd[4 * g + 2];
        }
        const int t0 = 4 * g;
        step(cb.x, c0.x, c1.x, rb0, t0);
        step(cb.y, c0.y, c1.y, rb1, t0 + 1);
        step(cb.z, c0.z, c1.z, rb2, t0 + 2);
        step(cb.w, c0.w, c1.w, rb3, t0 + 3);
        if (bnd && (g & 3) == 3) st_rel_(&sProg, 4 * (g + 1));
    }
    __syncthreads();

    // ---- tl==128: reconstruct slb (= bF series contribution) post-loop ----
    if (tl == 128){
        // CB_t = prefix sum of blank log2-emissions eb_1..eb_t (CB_0 = 0)
        const int t0 = tid * 16;
        float ebv[16];
        #pragma unroll
        for (int i = 0; i < 16; i += 4){
            const float4 e4 = ch[(size_t)((t0 + i) >> 2) * SLOTS_ + 128];
            ebv[i] = e4.x; ebv[i+1] = e4.y; ebv[i+2] = e4.z; ebv[i+3] = e4.w;
        }
        if (tid == 0) ebv[0] = 0.0f;           // eb_0 excluded
        float ps = 0.f;
        #pragma unroll
        for (int i = 0; i < 16; i++) ps += ebv[i];
        float inc = ps;                        // inclusive prefix across tids
        #pragma unroll
        for (int o = 1; o < 32; o <<= 1){
            const float v = __shfl_up_sync(~0u, inc, o);
            if (lane >= o) inc += v;
        }
        if (wid == 0 && lane == 31) sX[0] = inc;
        __syncthreads();
        float excl = inc - ps + ((wid == 1) ? sX[0] : 0.f);
        float cbv[16];
        float carry = excl, rmax = NEGF;
        #pragma unroll
        for (int i = 0; i < 16; i++){ carry += ebv[i]; cbv[i] = carry; rmax = fmaxf(rmax, carry); }
        float rsum = 0.f;
        #pragma unroll
        for (int i = 0; i < 16; i++) rsum += ex2f_(cbv[i] - rmax);
        const float rtot = rmax + lg2f_(rsum); // lse of CB over my 16 steps
        float suf = rtot;                      // inclusive suffix lse across tids
        #pragma unroll
        for (int o = 1; o < 32; o <<= 1){
            const float v = __shfl_down_sync(~0u, suf, o);
            if (lane + o < 32) suf = lse2_(suf, v);
        }
        if (wid == 1 && lane == 0) sX[1] = suf;
        __syncthreads();
        const float inclsuf = (wid == 0) ? lse2_(suf, sX[1]) : suf;
        const float nx = __shfl_down_sync(~0u, inclsuf, 1);
        float c2 = (lane == 31) ? ((wid == 0) ? sX[1] : NEGF) : nx;  // exclusive suffix
        #pragma unroll
        for (int i = 15; i >= 0; i--){
            const int t = t0 + i;
            slb[t] = sll[t] - cbv[i] + c2;     // RB_t = c2 (lse of CB_u, u>t)
            c2 = lse2_(c2, cbv[i]);
        }
        __syncthreads();
    }

    // ---- final reduction: total = lse over 2048 stored values ----
    float m = NEGF;
    for (int t = tid; t < T_; t += 64) m = fmaxf(m, fmaxf(sll[t], slb[t]));
    #pragma unroll
    for (int o = 16; o; o >>= 1) m = fmaxf(m, __shfl_xor_sync(~0u, m, o));
    if (lane == 0) red[wid] = m;
    __syncthreads();
    m = fmaxf(red[0], red[1]);
    float s = 0.f;
    for (int t = tid; t < T_; t += 64) s += ex2f_(sll[t] - m) + ex2f_(slb[t] - m);
    #pragma unroll
    for (int o = 16; o; o >>= 1) s += __shfl_xor_sync(~0u, s, o);
    __syncthreads();
    if (lane == 0) red[wid] = s;
    __syncthreads();
    if (tid == 0){
        const float tot2 = m + lg2f_(red[0] + red[1]);
        g_partial[b] = (-tot2 * LN2_) / (float)tl;
    }
}

// ---------------------------------------------------------------------------
// K3: mean over batches -> scalar
// ---------------------------------------------------------------------------
__global__ void k3_final(float* __restrict__ out){
    float v = (threadIdx.x < B_) ? g_partial[threadIdx.x] : 0.f;
    #pragma unroll
    for (int o = 16; o; o >>= 1) v += __shfl_xor_sync(~0u, v, o);
    if (threadIdx.x == 0) out[0] = v / (float)B_;
}

extern "C" void kernel_launch(void* const* d_in, const int* in_sizes, int n_in,
                              void* d_out, int out_size) {
    const float* pred   = (const float*)d_in[0];   // (B,T,V) f32
    const int*   target = (const int*)d_in[1];     // (B,L) i32
    const int*   tlen   = (const int*)d_in[2];     // (B,) i32
    (void)in_sizes; (void)n_in; (void)out_size;

    k1_emit<<<B_ * T_ / 8, 256>>>(pred, target, tlen);
    k2_dp<<<B_, 64>>>(target, tlen);
    k3_final<<<1, 32>>>((float*)d_out);
}